// round 1
// baseline (speedup 1.0000x reference)
#include <cuda_runtime.h>
#include <cuda_bf16.h>
#include <cstdint>

#define BB 8
#define LL 1024
#define NN 4096
#define DD 1024

// Scratch (allocation-free: __device__ globals)
static __device__ __nv_bfloat16 g_tn[(size_t)BB * LL * DD];        // 16 MB
static __device__ __nv_bfloat16 g_vn[(size_t)BB * NN * DD];        // 64 MB
static __device__ float g_S[BB * LL];                              // exp row sums
static __device__ float g_bn[BB * LL];                             // normalized beta

// ---------------------------------------------------------------------------
// Degree-4 polynomial exp, valid for |x| <= 1/32 (abs err ~3e-10)
__device__ __forceinline__ float exp_small(float x) {
    float p = fmaf(x, 1.0f / 24.0f, 1.0f / 6.0f);
    p = fmaf(x, p, 0.5f);
    p = fmaf(x, p, 1.0f);
    p = fmaf(x, p, 1.0f);
    return p;
}

__device__ __forceinline__ float block_reduce_256(float v, float* smem8) {
    int lane = threadIdx.x & 31, wid = threadIdx.x >> 5;
    #pragma unroll
    for (int o = 16; o; o >>= 1) v += __shfl_xor_sync(0xffffffffu, v, o);
    if (lane == 0) smem8[wid] = v;
    __syncthreads();
    float s = (threadIdx.x < 8) ? smem8[threadIdx.x] : 0.0f;
    if (wid == 0) {
        #pragma unroll
        for (int o = 4; o; o >>= 1) s += __shfl_xor_sync(0xffffffffu, s, o);
        if (lane == 0) smem8[0] = s;
    }
    __syncthreads();
    return smem8[0];
}

// ---------------------------------------------------------------------------
// Row L2-normalize fp32 -> bf16. One CTA (256 thr) per row of D=1024.
// which: 0 -> g_tn (also zero g_S), 1 -> g_vn
__global__ void __launch_bounds__(256) norm_rows_kernel(const float* __restrict__ in,
                                                        int which) {
    __shared__ float red[8];
    int row = blockIdx.x;
    const float4 v = reinterpret_cast<const float4*>(in + (size_t)row * DD)[threadIdx.x];
    float ss = v.x * v.x + v.y * v.y + v.z * v.z + v.w * v.w;
    ss = block_reduce_256(ss, red);
    float inv = 1.0f / fmaxf(sqrtf(ss), 1e-12f);

    __nv_bfloat16* out = which ? g_vn : g_tn;
    __nv_bfloat162* dst = reinterpret_cast<__nv_bfloat162*>(out + (size_t)row * DD);
    __nv_bfloat162 o0, o1;
    o0.x = __float2bfloat16(v.x * inv); o0.y = __float2bfloat16(v.y * inv);
    o1.x = __float2bfloat16(v.z * inv); o1.y = __float2bfloat16(v.w * inv);
    dst[threadIdx.x * 2 + 0] = o0;
    dst[threadIdx.x * 2 + 1] = o1;
    if (which == 0 && threadIdx.x == 0) g_S[row] = 0.0f;
}

// ---------------------------------------------------------------------------
// Normalize beta (masked) and zero s_ia region of output. One CTA per batch.
__global__ void __launch_bounds__(256) beta_kernel(const float* __restrict__ beta,
                                                   const int* __restrict__ mask,
                                                   float* __restrict__ sia) {
    __shared__ float red[8];
    int b = blockIdx.x;
    float s = 0.0f;
    for (int i = threadIdx.x; i < LL; i += 256) {
        float m = mask[b * LL + i] ? 1.0f : 0.0f;
        s += beta[b * LL + i] * m;
    }
    s = block_reduce_256(s, red);
    float inv = 1.0f / (s + 1e-8f);
    for (int i = threadIdx.x; i < LL; i += 256) {
        float m = mask[b * LL + i] ? 1.0f : 0.0f;
        g_bn[b * LL + i] = beta[b * LL + i] * m * inv;
    }
    for (int i = threadIdx.x; i < NN; i += 256)
        sia[(size_t)b * NN + i] = 0.0f;
}

// ---------------------------------------------------------------------------
// Fused GEMM + poly-exp. CTA tile 128(M) x 128(N), BK=32, 256 threads,
// 8 warps each computing 64x32 via mma.sync.m16n8k16 (bf16 -> f32).
// Writes unnormalized E = exp(logit) into Aout; accumulates row sums in g_S.
#define SLD 20  // smem row stride in uint32 (40 halves: 32 + 8 pad)

#define MMA16816(c0,c1,c2,c3,a0,a1,a2,a3,b0,b1)                                  \
    asm volatile("mma.sync.aligned.m16n8k16.row.col.f32.bf16.bf16.f32 "          \
                 "{%0,%1,%2,%3},{%4,%5,%6,%7},{%8,%9},{%0,%1,%2,%3};"            \
                 : "+f"(c0), "+f"(c1), "+f"(c2), "+f"(c3)                        \
                 : "r"(a0), "r"(a1), "r"(a2), "r"(a3), "r"(b0), "r"(b1))

__global__ void __launch_bounds__(256) gemm_exp_kernel(float* __restrict__ Aout) {
    __shared__ __align__(16) unsigned As[128 * SLD];
    __shared__ __align__(16) unsigned Bs[128 * SLD];

    const int b = blockIdx.z, mt = blockIdx.y, nt = blockIdx.x;
    const int tid = threadIdx.x, wid = tid >> 5, lane = tid & 31;
    const int wm = wid >> 2, wn = wid & 3;      // 2 x 4 warp grid
    const int gid = lane >> 2, qid = lane & 3;  // octet row / quad col

    const unsigned* gA = reinterpret_cast<const unsigned*>(g_tn) +
                         ((size_t)(b * LL + mt * 128)) * (DD / 2);
    const unsigned* gB = reinterpret_cast<const unsigned*>(g_vn) +
                         ((size_t)(b * NN + nt * 128)) * (DD / 2);

    float c[4][4][4];
    #pragma unroll
    for (int i = 0; i < 4; i++)
        #pragma unroll
        for (int j = 0; j < 4; j++)
            #pragma unroll
            for (int k = 0; k < 4; k++) c[i][j][k] = 0.0f;

    for (int k0 = 0; k0 < DD / 2; k0 += 16) {  // 16 uints = 32 halves per step
        __syncthreads();
        #pragma unroll
        for (int i = 0; i < 8; i++) {
            int idx = tid + i * 256;
            int r = idx >> 4, cc = idx & 15;
            As[r * SLD + cc] = gA[(size_t)r * 512 + k0 + cc];
            Bs[r * SLD + cc] = gB[(size_t)r * 512 + k0 + cc];
        }
        __syncthreads();

        #pragma unroll
        for (int kk = 0; kk < 2; kk++) {
            const int ko = kk * 8;  // uint offset for this k16
            unsigned a[4][4], bb[4][2];
            #pragma unroll
            for (int mf = 0; mf < 4; mf++) {
                int ra = wm * 64 + mf * 16;
                a[mf][0] = As[(ra + gid)     * SLD + ko + qid];
                a[mf][1] = As[(ra + 8 + gid) * SLD + ko + qid];
                a[mf][2] = As[(ra + gid)     * SLD + ko + 4 + qid];
                a[mf][3] = As[(ra + 8 + gid) * SLD + ko + 4 + qid];
            }
            #pragma unroll
            for (int nf = 0; nf < 4; nf++) {
                int cb = wn * 32 + nf * 8 + gid;
                bb[nf][0] = Bs[cb * SLD + ko + qid];
                bb[nf][1] = Bs[cb * SLD + ko + 4 + qid];
            }
            #pragma unroll
            for (int mf = 0; mf < 4; mf++)
                #pragma unroll
                for (int nf = 0; nf < 4; nf++)
                    MMA16816(c[mf][nf][0], c[mf][nf][1], c[mf][nf][2], c[mf][nf][3],
                             a[mf][0], a[mf][1], a[mf][2], a[mf][3],
                             bb[nf][0], bb[nf][1]);
        }
    }

    // Epilogue: scale by 1/32, poly-exp, store E, accumulate row sums.
    const float scale = 0.03125f;
    float* Abase = Aout + ((size_t)b * LL) * NN;
    #pragma unroll
    for (int mf = 0; mf < 4; mf++) {
        float rs0 = 0.0f, rs1 = 0.0f;
        int r0 = mt * 128 + wm * 64 + mf * 16 + gid;
        #pragma unroll
        for (int nf = 0; nf < 4; nf++) {
            int col = nt * 128 + wn * 32 + nf * 8 + qid * 2;
            float e00 = exp_small(c[mf][nf][0] * scale);
            float e01 = exp_small(c[mf][nf][1] * scale);
            float e10 = exp_small(c[mf][nf][2] * scale);
            float e11 = exp_small(c[mf][nf][3] * scale);
            *reinterpret_cast<float2*>(Abase + (size_t)r0 * NN + col)       = make_float2(e00, e01);
            *reinterpret_cast<float2*>(Abase + (size_t)(r0 + 8) * NN + col) = make_float2(e10, e11);
            rs0 += e00 + e01;
            rs1 += e10 + e11;
        }
        rs0 += __shfl_xor_sync(0xffffffffu, rs0, 1);
        rs0 += __shfl_xor_sync(0xffffffffu, rs0, 2);
        rs1 += __shfl_xor_sync(0xffffffffu, rs1, 1);
        rs1 += __shfl_xor_sync(0xffffffffu, rs1, 2);
        if (qid == 0) {
            atomicAdd(&g_S[b * LL + r0], rs0);
            atomicAdd(&g_S[b * LL + r0 + 8], rs1);
        }
    }
}

// ---------------------------------------------------------------------------
// Pass 2: A = E / S in place; s_ia[b,n] += sum_l bn[b,l] * A[b,l,n]
// Grid: (NN/256 colblocks, LL/128 lchunks, BB)
__global__ void __launch_bounds__(256) scale_sia_kernel(float* __restrict__ Aout,
                                                        float* __restrict__ sia) {
    __shared__ float invs[128], bns[128];
    const int b = blockIdx.z;
    const int l0 = blockIdx.y * 128;
    const int col = blockIdx.x * 256 + threadIdx.x;

    if (threadIdx.x < 128) {
        int l = l0 + threadIdx.x;
        invs[threadIdx.x] = 1.0f / g_S[b * LL + l];
        bns[threadIdx.x] = g_bn[b * LL + l];
    }
    __syncthreads();

    float acc = 0.0f;
    float* base = Aout + ((size_t)(b * LL + l0)) * NN + col;
    #pragma unroll 4
    for (int i = 0; i < 128; i++) {
        float v = base[(size_t)i * NN];
        float a = v * invs[i];
        base[(size_t)i * NN] = a;
        acc = fmaf(bns[i], a, acc);
    }
    atomicAdd(&sia[(size_t)b * NN + col], acc);
}

// ---------------------------------------------------------------------------
extern "C" void kernel_launch(void* const* d_in, const int* in_sizes, int n_in,
                              void* d_out, int out_size) {
    const float* text = (const float*)d_in[0];
    const float* vis  = (const float*)d_in[1];
    const float* beta = (const float*)d_in[2];
    const int*   mask = (const int*)d_in[3];

    float* out  = (float*)d_out;
    float* sia  = out;            // [B, N]
    float* Aout = out + BB * NN;  // [B, L, N]

    norm_rows_kernel<<<BB * LL, 256>>>(text, 0);
    norm_rows_kernel<<<BB * NN, 256>>>(vis, 1);
    beta_kernel<<<BB, 256>>>(beta, mask, sia);

    dim3 ggrid(NN / 128, LL / 128, BB);
    gemm_exp_kernel<<<ggrid, 256>>>(Aout);

    dim3 sgrid(NN / 256, LL / 128, BB);
    scale_sia_kernel<<<sgrid, 256>>>(Aout, sia);
}

// round 5
// speedup vs baseline: 1.6139x; 1.6139x over previous
#include <cuda_runtime.h>
#include <cuda_bf16.h>
#include <cstdint>

#define BB 8
#define LL 1024
#define NN 4096
#define DD 1024

// GEMM tiling: CTA 128x128, BK=64 halves (128 bytes/row), 3-stage cp.async
#define MT 128
#define NT 128
#define BK 64
#define NCHUNKS (DD / BK)                 // 16
#define STAGE_A_BYTES (MT * 128)          // 16384
#define STAGE_B_BYTES (NT * 128)          // 16384
#define STAGE_BYTES (STAGE_A_BYTES + STAGE_B_BYTES)   // 32768
#define SMEM_TOTAL (3 * STAGE_BYTES)      // 98304

// Scratch (allocation-free: __device__ globals)
static __device__ __nv_bfloat16 g_tn[(size_t)BB * LL * DD];        // 16 MB
static __device__ __nv_bfloat16 g_vn[(size_t)BB * NN * DD];        // 64 MB
static __device__ float g_S[BB * LL];                              // exp row sums
static __device__ float g_bn[BB * LL];                             // normalized beta

// ---------------------------------------------------------------------------
__device__ __forceinline__ uint32_t smem_u32(const void* p) {
    uint32_t a;
    asm("{ .reg .u64 t; cvta.to.shared.u64 t, %1; cvt.u32.u64 %0, t; }" : "=r"(a) : "l"(p));
    return a;
}
__device__ __forceinline__ void cp16(uint32_t dst, const void* src) {
    asm volatile("cp.async.cg.shared.global [%0], [%1], 16;" :: "r"(dst), "l"(src) : "memory");
}
__device__ __forceinline__ void cp_commit() { asm volatile("cp.async.commit_group;" ::: "memory"); }
__device__ __forceinline__ void cp_wait1()  { asm volatile("cp.async.wait_group 1;" ::: "memory"); }

__device__ __forceinline__ void ldsm4(uint32_t& r0, uint32_t& r1, uint32_t& r2, uint32_t& r3,
                                      uint32_t addr) {
    asm volatile("ldmatrix.sync.aligned.m8n8.x4.shared.b16 {%0,%1,%2,%3}, [%4];"
                 : "=r"(r0), "=r"(r1), "=r"(r2), "=r"(r3) : "r"(addr));
}

#define MMA16816(c0,c1,c2,c3,a0,a1,a2,a3,b0,b1)                                  \
    asm volatile("mma.sync.aligned.m16n8k16.row.col.f32.bf16.bf16.f32 "          \
                 "{%0,%1,%2,%3},{%4,%5,%6,%7},{%8,%9},{%0,%1,%2,%3};"            \
                 : "+f"(c0), "+f"(c1), "+f"(c2), "+f"(c3)                        \
                 : "r"(a0), "r"(a1), "r"(a2), "r"(a3), "r"(b0), "r"(b1))

// ---------------------------------------------------------------------------
// Degree-4 polynomial exp, valid for |x| <= 1/32 (abs err ~3e-10)
__device__ __forceinline__ float exp_small(float x) {
    float p = fmaf(x, 1.0f / 24.0f, 1.0f / 6.0f);
    p = fmaf(x, p, 0.5f);
    p = fmaf(x, p, 1.0f);
    p = fmaf(x, p, 1.0f);
    return p;
}

__device__ __forceinline__ float block_reduce_256(float v, float* smem8) {
    int lane = threadIdx.x & 31, wid = threadIdx.x >> 5;
    #pragma unroll
    for (int o = 16; o; o >>= 1) v += __shfl_xor_sync(0xffffffffu, v, o);
    if (lane == 0) smem8[wid] = v;
    __syncthreads();
    float s = (threadIdx.x < 8) ? smem8[threadIdx.x] : 0.0f;
    if (wid == 0) {
        #pragma unroll
        for (int o = 4; o; o >>= 1) s += __shfl_xor_sync(0xffffffffu, s, o);
        if (lane == 0) smem8[0] = s;
    }
    __syncthreads();
    return smem8[0];
}

// ---------------------------------------------------------------------------
// Row L2-normalize fp32 -> bf16. One CTA (256 thr) per row of D=1024.
__global__ void __launch_bounds__(256) norm_rows_kernel(const float* __restrict__ in,
                                                        int which) {
    __shared__ float red[8];
    int row = blockIdx.x;
    const float4 v = reinterpret_cast<const float4*>(in + (size_t)row * DD)[threadIdx.x];
    float ss = v.x * v.x + v.y * v.y + v.z * v.z + v.w * v.w;
    ss = block_reduce_256(ss, red);
    float inv = 1.0f / fmaxf(sqrtf(ss), 1e-12f);

    __nv_bfloat16* out = which ? g_vn : g_tn;
    __nv_bfloat162* dst = reinterpret_cast<__nv_bfloat162*>(out + (size_t)row * DD);
    __nv_bfloat162 o0, o1;
    o0.x = __float2bfloat16(v.x * inv); o0.y = __float2bfloat16(v.y * inv);
    o1.x = __float2bfloat16(v.z * inv); o1.y = __float2bfloat16(v.w * inv);
    dst[threadIdx.x * 2 + 0] = o0;
    dst[threadIdx.x * 2 + 1] = o1;
    if (which == 0 && threadIdx.x == 0) g_S[row] = 0.0f;
}

// ---------------------------------------------------------------------------
// Normalize beta (masked) and zero s_ia region of output. One CTA per batch.
__global__ void __launch_bounds__(256) beta_kernel(const float* __restrict__ beta,
                                                   const int* __restrict__ mask,
                                                   float* __restrict__ sia) {
    __shared__ float red[8];
    int b = blockIdx.x;
    float s = 0.0f;
    for (int i = threadIdx.x; i < LL; i += 256) {
        float m = mask[b * LL + i] ? 1.0f : 0.0f;
        s += beta[b * LL + i] * m;
    }
    s = block_reduce_256(s, red);
    float inv = 1.0f / (s + 1e-8f);
    for (int i = threadIdx.x; i < LL; i += 256) {
        float m = mask[b * LL + i] ? 1.0f : 0.0f;
        g_bn[b * LL + i] = beta[b * LL + i] * m * inv;
    }
    for (int i = threadIdx.x; i < NN; i += 256)
        sia[(size_t)b * NN + i] = 0.0f;
}

// ---------------------------------------------------------------------------
// mma.sync GEMM + poly-exp. CTA tile 128x128, 8 warps (2x4), warp tile 64x32.
// ldmatrix.x4 operand loads from SW128-swizzled smem; 3-stage cp.async pipeline.
__global__ void __launch_bounds__(256)
gemm_exp_kernel(float* __restrict__ Aout) {
    extern __shared__ __align__(1024) char smem[];
    const uint32_t sbase = smem_u32(smem);
    const int tid = threadIdx.x, wid = tid >> 5, lane = tid & 31;
    const int b = blockIdx.z, mt = blockIdx.y, nt = blockIdx.x;
    const int wm = wid >> 2, wn = wid & 3;      // 2 x 4 warp grid
    const int gid = lane >> 2, qid = lane & 3;  // mma accum layout

    const char* pA = (const char*)g_tn + ((size_t)(b * LL + mt * MT)) * (DD * 2);
    const char* pB = (const char*)g_vn + ((size_t)(b * NN + nt * NT)) * (DD * 2);

    // Fill one stage (A rows 0..127 + B rows 0..127), 128B per row, swizzled.
    #define FILL(cc, stage) do {                                                        \
        uint32_t sA = sbase + (stage) * STAGE_BYTES;                                    \
        uint32_t sB = sA + STAGE_A_BYTES;                                               \
        const char* srcA = pA + (cc) * 128;                                             \
        const char* srcB = pB + (cc) * 128;                                             \
        _Pragma("unroll")                                                               \
        for (int i = 0; i < 4; i++) {                                                   \
            int seg = tid + i * 256;                                                    \
            int row = seg >> 3, s16 = (seg & 7) * 16;                                   \
            int off = row * 128 + s16;                                                  \
            uint32_t sw = off ^ ((off >> 3) & 0x70);                                    \
            cp16(sA + sw, srcA + (size_t)row * 2048 + s16);                             \
            cp16(sB + sw, srcB + (size_t)row * 2048 + s16);                             \
        }                                                                               \
    } while (0)

    // ldmatrix lane addressing (precomputed row bases + swizzle XOR values)
    const int matq = lane >> 3, laneR = lane & 7;   // quad index, row-in-8x8
    // A: mat0=(m0,k0) mat1=(m0+8,k0) mat2=(m0,k0+8) mat3=(m0+8,k0+8)
    int aRowBase[4], aXor[4];
    #pragma unroll
    for (int mf = 0; mf < 4; mf++) {
        int r = wm * 64 + mf * 16 + (matq & 1) * 8 + laneR;
        aRowBase[mf] = r * 128;
        aXor[mf] = (r & 7) << 4;
    }
    const int aKoff = (matq >> 1) * 16;  // byte offset within k16 (halves*2)
    // B: mat0=(n0,k0) mat1=(n0,k0+8) mat2=(n0+8,k0) mat3=(n0+8,k0+8)
    int bRowBase[2], bXor[2];
    #pragma unroll
    for (int p = 0; p < 2; p++) {
        int r = wn * 32 + p * 16 + (matq >> 1) * 8 + laneR;
        bRowBase[p] = r * 128;
        bXor[p] = (r & 7) << 4;
    }
    const int bKoff = (matq & 1) * 16;

    float c[4][4][4];
    #pragma unroll
    for (int i = 0; i < 4; i++)
        #pragma unroll
        for (int j = 0; j < 4; j++)
            #pragma unroll
            for (int k = 0; k < 4; k++) c[i][j][k] = 0.0f;

    FILL(0, 0); cp_commit();
    FILL(1, 1); cp_commit();

    #pragma unroll 1
    for (int cc = 0; cc < NCHUNKS; cc++) {
        cp_wait1();          // stage cc's data resident (<=1 group pending)
        __syncthreads();     // all warps done reading stage (cc+2)%3 (iter cc-1)
        if (cc + 2 < NCHUNKS) FILL(cc + 2, (cc + 2) % 3);
        cp_commit();

        const uint32_t sA = sbase + (cc % 3) * STAGE_BYTES;
        const uint32_t sB = sA + STAGE_A_BYTES;

        #pragma unroll
        for (int ks = 0; ks < 4; ks++) {
            const int kb = ks * 32;  // byte offset of this k16 within the 128B row
            uint32_t a[4][4], bb[4][2];
            #pragma unroll
            for (int mf = 0; mf < 4; mf++) {
                uint32_t addr = sA + aRowBase[mf] + ((kb + aKoff) ^ aXor[mf]);
                ldsm4(a[mf][0], a[mf][1], a[mf][2], a[mf][3], addr);
            }
            #pragma unroll
            for (int p = 0; p < 2; p++) {
                uint32_t addr = sB + bRowBase[p] + ((kb + bKoff) ^ bXor[p]);
                ldsm4(bb[2*p][0], bb[2*p][1], bb[2*p+1][0], bb[2*p+1][1], addr);
            }
            #pragma unroll
            for (int mf = 0; mf < 4; mf++)
                #pragma unroll
                for (int nf = 0; nf < 4; nf++)
                    MMA16816(c[mf][nf][0], c[mf][nf][1], c[mf][nf][2], c[mf][nf][3],
                             a[mf][0], a[mf][1], a[mf][2], a[mf][3],
                             bb[nf][0], bb[nf][1]);
        }
    }

    // Epilogue: scale by 1/32, poly-exp, store E, accumulate row sums.
    const float scale = 0.03125f;
    float* Abase = Aout + ((size_t)b * LL) * NN;
    #pragma unroll
    for (int mf = 0; mf < 4; mf++) {
        float rs0 = 0.0f, rs1 = 0.0f;
        int r0 = mt * MT + wm * 64 + mf * 16 + gid;
        #pragma unroll
        for (int nf = 0; nf < 4; nf++) {
            int col = nt * NT + wn * 32 + nf * 8 + qid * 2;
            float e00 = exp_small(c[mf][nf][0] * scale);
            float e01 = exp_small(c[mf][nf][1] * scale);
            float e10 = exp_small(c[mf][nf][2] * scale);
            float e11 = exp_small(c[mf][nf][3] * scale);
            *reinterpret_cast<float2*>(Abase + (size_t)r0 * NN + col)       = make_float2(e00, e01);
            *reinterpret_cast<float2*>(Abase + (size_t)(r0 + 8) * NN + col) = make_float2(e10, e11);
            rs0 += e00 + e01;
            rs1 += e10 + e11;
        }
        rs0 += __shfl_xor_sync(0xffffffffu, rs0, 1);
        rs0 += __shfl_xor_sync(0xffffffffu, rs0, 2);
        rs1 += __shfl_xor_sync(0xffffffffu, rs1, 1);
        rs1 += __shfl_xor_sync(0xffffffffu, rs1, 2);
        if (qid == 0) {
            atomicAdd(&g_S[b * LL + r0], rs0);
            atomicAdd(&g_S[b * LL + r0 + 8], rs1);
        }
    }
    #undef FILL
}

// ---------------------------------------------------------------------------
// Pass 2: A = E / S in place; s_ia[b,n] += sum_l bn[b,l] * A[b,l,n]
__global__ void __launch_bounds__(256) scale_sia_kernel(float* __restrict__ Aout,
                                                        float* __restrict__ sia) {
    __shared__ float invs[128], bns[128];
    const int b = blockIdx.z;
    const int l0 = blockIdx.y * 128;
    const int col = blockIdx.x * 256 + threadIdx.x;

    if (threadIdx.x < 128) {
        int l = l0 + threadIdx.x;
        invs[threadIdx.x] = 1.0f / g_S[b * LL + l];
        bns[threadIdx.x] = g_bn[b * LL + l];
    }
    __syncthreads();

    float acc = 0.0f;
    float* base = Aout + ((size_t)(b * LL + l0)) * NN + col;
    #pragma unroll 4
    for (int i = 0; i < 128; i++) {
        float v = base[(size_t)i * NN];
        float a = v * invs[i];
        base[(size_t)i * NN] = a;
        acc = fmaf(bns[i], a, acc);
    }
    atomicAdd(&sia[(size_t)b * NN + col], acc);
}

// ---------------------------------------------------------------------------
extern "C" void kernel_launch(void* const* d_in, const int* in_sizes, int n_in,
                              void* d_out, int out_size) {
    const float* text = (const float*)d_in[0];
    const float* vis  = (const float*)d_in[1];
    const float* beta = (const float*)d_in[2];
    const int*   mask = (const int*)d_in[3];

    float* out  = (float*)d_out;
    float* sia  = out;            // [B, N]
    float* Aout = out + BB * NN;  // [B, L, N]

    norm_rows_kernel<<<BB * LL, 256>>>(text, 0);
    norm_rows_kernel<<<BB * NN, 256>>>(vis, 1);
    beta_kernel<<<BB, 256>>>(beta, mask, sia);

    cudaFuncSetAttribute(gemm_exp_kernel,
                         cudaFuncAttributeMaxDynamicSharedMemorySize, SMEM_TOTAL);
    dim3 ggrid(NN / NT, LL / MT, BB);
    gemm_exp_kernel<<<ggrid, 256, SMEM_TOTAL>>>(Aout);

    dim3 sgrid(NN / 256, LL / 128, BB);
    scale_sia_kernel<<<sgrid, 256>>>(Aout, sia);
}